// round 2
// baseline (speedup 1.0000x reference)
#include <cuda_runtime.h>
#include <cuda_bf16.h>

// KPConv: out[p,o] = sum_{k,i} exp(-0.5*d2(p,k)/sigma^2) * x[p,i] * W[k,i,o]
// B=8, N=65536 -> 524288 points, K=16, CIN=3 (J=48), COUT=64.
//
// Strategy: per-warp two-phase.
//   Phase 1: lane L computes a_j = g_k * x_i (j=k*3+i, 48 values) for point
//            (groupBase+L), stores row to shared (stride 52 floats, 16B aligned).
//   Phase 2: lane c owns output channels (2c, 2c+1); W column pair held in
//            registers as 48 packed u64 (float2). For each of the 32 points,
//            broadcast-load a row via LDS.128 and do 48 fma.rn.f32x2.

#define KP_   16
#define JDIM  48
#define COUT_ 64
#define WARPS 4
#define ASTRIDE 52   // 48 + pad; 52*4 = 208 bytes, 16B aligned rows

__global__ __launch_bounds__(WARPS * 32, 4)
void kpconv_kernel(const float* __restrict__ x,
                   const float* __restrict__ kpts,
                   const float* __restrict__ wts,
                   const float* __restrict__ sigma,
                   float* __restrict__ out,
                   int npts)
{
    __shared__ __align__(16) float sA[WARPS][32][ASTRIDE];
    __shared__ float sKP[JDIM];

    const int tid  = threadIdx.x;
    const int lane = tid & 31;
    const int w    = tid >> 5;

    if (tid < JDIM) sKP[tid] = kpts[tid];
    __syncthreads();

    const float sg = sigma[0];
    const float cc = -0.5f / (sg * sg);   // exponent coefficient (use __expf)

    // Load this lane's weight column pair: W[j][2*lane], W[j][2*lane+1], packed.
    unsigned long long wr[JDIM];
#pragma unroll
    for (int j = 0; j < JDIM; j++) {
        float2 wv = *reinterpret_cast<const float2*>(wts + j * COUT_ + 2 * lane);
        asm("mov.b64 %0, {%1, %2};" : "=l"(wr[j]) : "f"(wv.x), "f"(wv.y));
    }

    const int warpGlobal = blockIdx.x * WARPS + w;
    const int numWarps   = gridDim.x * WARPS;
    const int numGroups  = (npts + 31) >> 5;

    for (int grp = warpGlobal; grp < numGroups; grp += numWarps) {
        const int base = grp << 5;
        const int p    = base + lane;

        // ---- Phase 1: coefficients for my point ----
        float x0 = 0.f, x1 = 0.f, x2 = 0.f;
        if (p < npts) {
            x0 = x[p * 3 + 0];
            x1 = x[p * 3 + 1];
            x2 = x[p * 3 + 2];
        }
        float* arow = sA[w][lane];
#pragma unroll
        for (int k = 0; k < KP_; k++) {
            float dx = x0 - sKP[3 * k + 0];
            float dy = x1 - sKP[3 * k + 1];
            float dz = x2 - sKP[3 * k + 2];
            float d2 = dx * dx + dy * dy + dz * dz;
            float g  = __expf(cc * d2);     // MUFU.EX2 path
            arow[3 * k + 0] = g * x0;
            arow[3 * k + 1] = g * x1;
            arow[3 * k + 2] = g * x2;
        }
        __syncwarp();

        // ---- Phase 2: 32 points x 64 channels via f32x2 FMA ----
        const int nValid = (npts - base >= 32) ? 32 : (npts - base);
        for (int q = 0; q < nValid; q++) {
            const float4* a4 = reinterpret_cast<const float4*>(sA[w][q]);
            unsigned long long acc0 = 0ull, acc1 = 0ull;
#pragma unroll
            for (int jj = 0; jj < JDIM / 4; jj++) {
                float4 v = a4[jj];
                unsigned long long b0, b1, b2, b3;
                asm("mov.b64 %0, {%1, %1};" : "=l"(b0) : "r"(__float_as_uint(v.x)));
                asm("mov.b64 %0, {%1, %1};" : "=l"(b1) : "r"(__float_as_uint(v.y)));
                asm("mov.b64 %0, {%1, %1};" : "=l"(b2) : "r"(__float_as_uint(v.z)));
                asm("mov.b64 %0, {%1, %1};" : "=l"(b3) : "r"(__float_as_uint(v.w)));
                asm("fma.rn.f32x2 %0, %1, %2, %3;"
                    : "=l"(acc0) : "l"(b0), "l"(wr[4 * jj + 0]), "l"(acc0));
                asm("fma.rn.f32x2 %0, %1, %2, %3;"
                    : "=l"(acc1) : "l"(b1), "l"(wr[4 * jj + 1]), "l"(acc1));
                asm("fma.rn.f32x2 %0, %1, %2, %3;"
                    : "=l"(acc0) : "l"(b2), "l"(wr[4 * jj + 2]), "l"(acc0));
                asm("fma.rn.f32x2 %0, %1, %2, %3;"
                    : "=l"(acc1) : "l"(b3), "l"(wr[4 * jj + 3]), "l"(acc1));
            }
            unsigned long long accs;
            asm("add.rn.f32x2 %0, %1, %2;" : "=l"(accs) : "l"(acc0), "l"(acc1));
            *reinterpret_cast<unsigned long long*>(
                out + (unsigned long long)(base + q) * COUT_ + 2 * lane) = accs;
        }
        __syncwarp();
    }
}

extern "C" void kernel_launch(void* const* d_in, const int* in_sizes, int n_in,
                              void* d_out, int out_size)
{
    // Identify inputs robustly by element count:
    //   x: B*N*CIN = 1572864, kernel_points: 48, weights: 3072, sigma: 1
    const float* x  = nullptr;
    const float* kp = nullptr;
    const float* wt = nullptr;
    const float* sg = nullptr;
    int x_elems = 0;
    for (int i = 0; i < n_in; i++) {
        int s = in_sizes[i];
        if (s == 1)        sg = (const float*)d_in[i];
        else if (s == JDIM)  kp = (const float*)d_in[i];
        else if (s == KP_ * 3 * COUT_) wt = (const float*)d_in[i];
        else { x = (const float*)d_in[i]; x_elems = s; }
    }

    const int npts = x_elems / 3;
    float* out = (float*)d_out;

    // 148 SMs * 4 resident blocks (reg-limited at ~128 regs/thread)
    dim3 grid(148 * 4);
    dim3 block(WARPS * 32);
    kpconv_kernel<<<grid, block>>>(x, kp, wt, sg, out, npts);
}

// round 5
// speedup vs baseline: 1.4878x; 1.4878x over previous
#include <cuda_runtime.h>
#include <cuda_bf16.h>
#include <cstdint>

// KPConv as warp-MMA GEMM (sm_103-safe PTX: ldmatrix + mma.sync bf16):
//   A[p, j] = exp(-0.5*d2(p,k)/sigma^2) * x[p,i]   (j = 3k+i, 48 cols = 3 k-tiles)
//   out[p,n] = A @ W, W[48][64].
// fp32 via bf16 split: D = Ah*Wh + Al*Wh + Ah*Wl (fp32 accum).

#define KP_    16
#define JDIM   48
#define COUT_  64
#define NTHR   128
#define TILE_M 64
#define ROWB   112                     // A row stride bytes (48 bf16 + pad, conflict-free)
#define SM_AH  0
#define SM_AL  (TILE_M * ROWB)         // 7168
#define SM_TOTAL (2 * TILE_M * ROWB)   // 14336 (W staging 12288B aliased at offset 0)

__device__ __forceinline__ uint32_t smem_u32(const void* p) {
    uint32_t a;
    asm("{ .reg .u64 t; cvta.to.shared.u64 t, %1; cvt.u32.u64 %0, t; }" : "=r"(a) : "l"(p));
    return a;
}
__device__ __forceinline__ uint32_t pack_bf(float lo, float hi) {
    uint32_t bl = (uint32_t)__bfloat16_as_ushort(__float2bfloat16_rn(lo));
    uint32_t bh = (uint32_t)__bfloat16_as_ushort(__float2bfloat16_rn(hi));
    return bl | (bh << 16);
}
// split f into bf16 hi + bf16 lo residual (as floats for re-packing)
__device__ __forceinline__ void split2(float f, float& h, float& l) {
    h = __bfloat162float(__float2bfloat16_rn(f));
    l = f - h;
}
__device__ __forceinline__ void ldsm_x4(uint32_t* r, uint32_t addr) {
    asm volatile("ldmatrix.sync.aligned.m8n8.x4.shared.b16 {%0,%1,%2,%3}, [%4];"
                 : "=r"(r[0]), "=r"(r[1]), "=r"(r[2]), "=r"(r[3]) : "r"(addr));
}
__device__ __forceinline__ void mma_bf16(float* c, const uint32_t* a, const uint32_t* b) {
    asm volatile(
        "mma.sync.aligned.m16n8k16.row.col.f32.bf16.bf16.f32 "
        "{%0,%1,%2,%3}, {%4,%5,%6,%7}, {%8,%9}, {%0,%1,%2,%3};"
        : "+f"(c[0]), "+f"(c[1]), "+f"(c[2]), "+f"(c[3])
        : "r"(a[0]), "r"(a[1]), "r"(a[2]), "r"(a[3]), "r"(b[0]), "r"(b[1]));
}

__global__ __launch_bounds__(NTHR)
void kpconv_wmma_kernel(const float* __restrict__ x,
                        const float* __restrict__ kpts,
                        const float* __restrict__ wts,
                        const float* __restrict__ sigma,
                        float* __restrict__ out,
                        int npts)
{
    extern __shared__ char smem[];
    const uint32_t sb = smem_u32(smem);
    const int tid  = threadIdx.x;
    const int wid  = tid >> 5;
    const int lane = tid & 31;
    const int gid  = lane >> 2;   // 0..7
    const int tig  = lane & 3;    // 0..3

    __shared__ float sKP[JDIM];
    if (tid < JDIM) sKP[tid] = kpts[tid];

    // ---- Phase 0: stage W to smem (aliased with A region), build B fragments ----
    float* sWf = reinterpret_cast<float*>(smem);
    for (int i = tid; i < JDIM * COUT_; i += NTHR) sWf[i] = wts[i];
    __syncthreads();

    uint32_t Bh[8][3][2], Bl[8][3][2];
#pragma unroll
    for (int nt = 0; nt < 8; nt++) {
#pragma unroll
        for (int kt = 0; kt < 3; kt++) {
            int n  = nt * 8 + gid;
            int j0 = kt * 16 + 2 * tig;
            float w00 = sWf[(j0    ) * COUT_ + n], w01 = sWf[(j0 + 1) * COUT_ + n];
            float w10 = sWf[(j0 + 8) * COUT_ + n], w11 = sWf[(j0 + 9) * COUT_ + n];
            float h, l, h2, l2;
            split2(w00, h, l); split2(w01, h2, l2);
            Bh[nt][kt][0] = pack_bf(h, h2);  Bl[nt][kt][0] = pack_bf(l, l2);
            split2(w10, h, l); split2(w11, h2, l2);
            Bh[nt][kt][1] = pack_bf(h, h2);  Bl[nt][kt][1] = pack_bf(l, l2);
        }
    }
    __syncthreads();   // W staging consumed; smem now owned by A tiles

    const float sg = sigma[0];
    const float cc = -0.5f / (sg * sg);

    // ldmatrix lane address pattern (within a warp's 16-row m-tile)
    const int lrow = (lane & 7) + ((lane >> 3) & 1) * 8;
    const int lcol = lane >> 4;                       // 0/1 -> k-chunk
    const uint32_t lmoff = (uint32_t)lrow * ROWB + (uint32_t)lcol * 16;

    const int ntiles = (npts + TILE_M - 1) / TILE_M;

    for (int t = blockIdx.x; t < ntiles; t += gridDim.x) {
        const int base = t * TILE_M;

        // ---- Phase 1: thread computes half an A-row (8 kernel points) ----
        {
            const int r  = tid >> 1;              // 0..63
            const int kh = (tid & 1) * 8;         // k range start
            const int p  = base + r;
            float x0 = 0.f, x1 = 0.f, x2 = 0.f;
            if (p < npts) { x0 = x[3 * p]; x1 = x[3 * p + 1]; x2 = x[3 * p + 2]; }
            float a[24];
#pragma unroll
            for (int kk = 0; kk < 8; kk++) {
                const int k = kh + kk;
                float dx = x0 - sKP[3 * k], dy = x1 - sKP[3 * k + 1], dz = x2 - sKP[3 * k + 2];
                float g = __expf(cc * (dx * dx + dy * dy + dz * dz));
                a[3 * kk] = g * x0; a[3 * kk + 1] = g * x1; a[3 * kk + 2] = g * x2;
            }
            uint32_t hv[12], lv[12];
#pragma unroll
            for (int m = 0; m < 12; m++) {
                float h0, l0, h1, l1;
                split2(a[2 * m], h0, l0);
                split2(a[2 * m + 1], h1, l1);
                hv[m] = pack_bf(h0, h1);
                lv[m] = pack_bf(l0, l1);
            }
            char* rh = smem + SM_AH + r * ROWB + kh * 6;
            char* rl = smem + SM_AL + r * ROWB + kh * 6;
#pragma unroll
            for (int q = 0; q < 3; q++) {
                *reinterpret_cast<uint4*>(rh + q * 16) =
                    make_uint4(hv[4 * q], hv[4 * q + 1], hv[4 * q + 2], hv[4 * q + 3]);
                *reinterpret_cast<uint4*>(rl + q * 16) =
                    make_uint4(lv[4 * q], lv[4 * q + 1], lv[4 * q + 2], lv[4 * q + 3]);
            }
        }
        __syncthreads();

        // ---- Phase 2: warp wid owns m-tile rows [wid*16, wid*16+16) x all 64 cols ----
        float acc[8][4];
#pragma unroll
        for (int nt = 0; nt < 8; nt++)
#pragma unroll
            for (int c = 0; c < 4; c++) acc[nt][c] = 0.f;

        const uint32_t abase_h = sb + SM_AH + (uint32_t)(wid * 16) * ROWB + lmoff;
        const uint32_t abase_l = sb + SM_AL + (uint32_t)(wid * 16) * ROWB + lmoff;
#pragma unroll
        for (int kt = 0; kt < 3; kt++) {
            uint32_t ah[4], al[4];
            ldsm_x4(ah, abase_h + kt * 32);
            ldsm_x4(al, abase_l + kt * 32);
#pragma unroll
            for (int nt = 0; nt < 8; nt++) {
                mma_bf16(acc[nt], ah, Bh[nt][kt]);
                mma_bf16(acc[nt], al, Bh[nt][kt]);
                mma_bf16(acc[nt], ah, Bl[nt][kt]);
            }
        }

        // ---- Epilogue: direct STG.64 per fragment ----
        const int row0 = base + wid * 16 + gid;
#pragma unroll
        for (int nt = 0; nt < 8; nt++) {
            const int col = nt * 8 + 2 * tig;
            if (row0 < npts)
                *reinterpret_cast<float2*>(out + (size_t)row0 * COUT_ + col) =
                    make_float2(acc[nt][0], acc[nt][1]);
            if (row0 + 8 < npts)
                *reinterpret_cast<float2*>(out + (size_t)(row0 + 8) * COUT_ + col) =
                    make_float2(acc[nt][2], acc[nt][3]);
        }
        __syncthreads();   // all warps done reading A before next phase-1 overwrite
    }
}

extern "C" void kernel_launch(void* const* d_in, const int* in_sizes, int n_in,
                              void* d_out, int out_size)
{
    const float *x = nullptr, *kp = nullptr, *wt = nullptr, *sg = nullptr;
    int x_elems = 0;
    for (int i = 0; i < n_in; i++) {
        int s = in_sizes[i];
        if (s == 1)                    sg = (const float*)d_in[i];
        else if (s == JDIM)            kp = (const float*)d_in[i];
        else if (s == KP_ * 3 * COUT_) wt = (const float*)d_in[i];
        else { x = (const float*)d_in[i]; x_elems = s; }
    }
    const int npts = x_elems / 3;
    const int ntiles = (npts + TILE_M - 1) / TILE_M;
    int grid = 148 * 3;
    if (grid > ntiles) grid = ntiles;

    kpconv_wmma_kernel<<<grid, NTHR, SM_TOTAL>>>(x, kp, wt, sg, (float*)d_out, npts);
}

// round 6
// speedup vs baseline: 1.8890x; 1.2697x over previous
#include <cuda_runtime.h>
#include <cuda_bf16.h>
#include <cstdint>

// KPConv as warp-MMA GEMM, warp-independent tiles (no block barriers in loop):
//   A[p, j] = exp(-0.5*d2(p,k)/sigma^2) * x[p,i]   (j = 3k+i, 48 cols = 3 k-tiles)
//   out = A @ W.  fp32 via bf16 split: D = Ah*Wh + Al*Wh + Ah*Wl.
// Each warp owns a 16-row tile: phase1 build A (hi/lo bf16, smem stride 144B,
// conflict-free), phase2 ldmatrix + 72 mma.sync, epilogue shfl-butterfly ->
// STG.128 (64B-per-row segments).

#define KP_    16
#define JDIM   48
#define COUT_  64
#define NTHR   128
#define ROWB   144                    // A row stride bytes (balanced banks)
#define AWARP  (16 * ROWB)            // 2304 B per (warp, half)

__device__ __forceinline__ uint32_t smem_u32(const void* p) {
    uint32_t a;
    asm("{ .reg .u64 t; cvta.to.shared.u64 t, %1; cvt.u32.u64 %0, t; }" : "=r"(a) : "l"(p));
    return a;
}
__device__ __forceinline__ uint32_t pack_bf_rn(float lo, float hi) {
    uint32_t r;
    asm("cvt.rn.bf16x2.f32 %0, %1, %2;" : "=r"(r) : "f"(hi), "f"(lo));
    return r;
}
__device__ __forceinline__ void ldsm_x4(uint32_t* r, uint32_t addr) {
    asm volatile("ldmatrix.sync.aligned.m8n8.x4.shared.b16 {%0,%1,%2,%3}, [%4];"
                 : "=r"(r[0]), "=r"(r[1]), "=r"(r[2]), "=r"(r[3]) : "r"(addr));
}
__device__ __forceinline__ void mma_bf16(float* c, const uint32_t* a, const uint32_t* b) {
    asm volatile(
        "mma.sync.aligned.m16n8k16.row.col.f32.bf16.bf16.f32 "
        "{%0,%1,%2,%3}, {%4,%5,%6,%7}, {%8,%9}, {%0,%1,%2,%3};"
        : "+f"(c[0]), "+f"(c[1]), "+f"(c[2]), "+f"(c[3])
        : "r"(a[0]), "r"(a[1]), "r"(a[2]), "r"(a[3]), "r"(b[0]), "r"(b[1]));
}

__global__ __launch_bounds__(NTHR, 3)
void kpconv_wmma2_kernel(const float* __restrict__ x,
                         const float* __restrict__ kpts,
                         const float* __restrict__ wts,
                         const float* __restrict__ sigma,
                         float* __restrict__ out,
                         int npts)
{
    // per-warp A staging: [warp][hi/lo][16 rows x 144B]; W staged (aliased) once.
    __shared__ __align__(16) char sA[4][2][AWARP];   // 18432 B
    __shared__ float sKP[JDIM];

    const int tid  = threadIdx.x;
    const int wid  = tid >> 5;
    const int lane = tid & 31;
    const int gid  = lane >> 2;   // 0..7
    const int tig  = lane & 3;    // 0..3

    if (tid < JDIM) sKP[tid] = kpts[tid];

    // ---- one-time: stage W (aliased into sA), build B fragments in regs ----
    float* sWf = reinterpret_cast<float*>(&sA[0][0][0]);   // 12288 <= 18432
    for (int i = tid; i < JDIM * COUT_; i += NTHR) sWf[i] = wts[i];
    __syncthreads();

    uint32_t Bh[8][3][2], Bl[8][3][2];
#pragma unroll
    for (int nt = 0; nt < 8; nt++) {
#pragma unroll
        for (int kt = 0; kt < 3; kt++) {
            int n  = nt * 8 + gid;
            int j0 = kt * 16 + 2 * tig;
#pragma unroll
            for (int h = 0; h < 2; h++) {           // k-half 0/1
                float w0 = sWf[(j0 + 8 * h    ) * COUT_ + n];
                float w1 = sWf[(j0 + 8 * h + 1) * COUT_ + n];
                float h0 = __bfloat162float(__float2bfloat16_rn(w0));
                float h1 = __bfloat162float(__float2bfloat16_rn(w1));
                Bh[nt][kt][h] = pack_bf_rn(h0, h1);
                Bl[nt][kt][h] = pack_bf_rn(w0 - h0, w1 - h1);
            }
        }
    }
    __syncthreads();   // W staging dead; sA belongs to warps now

    const float sg = sigma[0];
    const float cc = -0.5f / (sg * sg);

    const uint32_t aHi = smem_u32(&sA[wid][0][0]);
    const uint32_t aLo = smem_u32(&sA[wid][1][0]);
    // ldmatrix lane address offset within the 16-row tile
    const uint32_t lmoff = (uint32_t)(lane & 15) * ROWB + (uint32_t)(lane >> 4) * 16;

    const int ngroups  = (npts + 15) >> 4;
    const int warpGlob = blockIdx.x * 4 + wid;
    const int numWarps = gridDim.x * 4;

    for (int grp = warpGlob; grp < ngroups; grp += numWarps) {
        const int base = grp << 4;

        // ---- phase 1: lane (r = lane>>1) computes k-half (lane&1) of row r ----
        {
            const int r  = lane >> 1;
            const int kh = (lane & 1) * 8;
            const int p  = base + r;
            float x0 = 0.f, x1 = 0.f, x2 = 0.f;
            if (p < npts) { x0 = x[3 * p]; x1 = x[3 * p + 1]; x2 = x[3 * p + 2]; }
            float a[24];
#pragma unroll
            for (int kk = 0; kk < 8; kk++) {
                const int k = kh + kk;
                float dx = x0 - sKP[3 * k], dy = x1 - sKP[3 * k + 1], dz = x2 - sKP[3 * k + 2];
                float g = __expf(cc * (dx * dx + dy * dy + dz * dz));
                a[3 * kk] = g * x0; a[3 * kk + 1] = g * x1; a[3 * kk + 2] = g * x2;
            }
            uint32_t hv[12], lv[12];
#pragma unroll
            for (int m = 0; m < 12; m++) {
                float ae = a[2 * m], ao = a[2 * m + 1];
                float he = __uint_as_float(__float_as_uint(ae) & 0xFFFF0000u);
                float ho = __uint_as_float(__float_as_uint(ao) & 0xFFFF0000u);
                asm("prmt.b32 %0, %1, %2, 0x7632;"
                    : "=r"(hv[m]) : "r"(__float_as_uint(ae)), "r"(__float_as_uint(ao)));
                lv[m] = pack_bf_rn(ae - he, ao - ho);
            }
            char* rh = &sA[wid][0][0] + r * ROWB + (kh >> 3) * 48;
            char* rl = &sA[wid][1][0] + r * ROWB + (kh >> 3) * 48;
#pragma unroll
            for (int q = 0; q < 3; q++) {
                *reinterpret_cast<uint4*>(rh + q * 16) =
                    make_uint4(hv[4 * q], hv[4 * q + 1], hv[4 * q + 2], hv[4 * q + 3]);
                *reinterpret_cast<uint4*>(rl + q * 16) =
                    make_uint4(lv[4 * q], lv[4 * q + 1], lv[4 * q + 2], lv[4 * q + 3]);
            }
        }
        __syncwarp();

        // ---- phase 2: 3 k-tiles x (3 passes x 8 n-tiles) ----
        float acc[8][4];
#pragma unroll
        for (int nt = 0; nt < 8; nt++)
#pragma unroll
            for (int c = 0; c < 4; c++) acc[nt][c] = 0.f;

#pragma unroll
        for (int kt = 0; kt < 3; kt++) {
            uint32_t ah[4], al[4];
            ldsm_x4(ah, aHi + lmoff + kt * 32);
            ldsm_x4(al, aLo + lmoff + kt * 32);
#pragma unroll
            for (int nt = 0; nt < 8; nt++) mma_bf16(acc[nt], ah, Bh[nt][kt]);
#pragma unroll
            for (int nt = 0; nt < 8; nt++) mma_bf16(acc[nt], al, Bh[nt][kt]);
#pragma unroll
            for (int nt = 0; nt < 8; nt++) mma_bf16(acc[nt], ah, Bl[nt][kt]);
        }

        // ---- epilogue: butterfly (xor 1) -> float4 -> STG.128 (64B/row runs) ----
        const int rowLo = base + gid;
        const int rowHi = rowLo + 8;
        const bool ev   = (tig & 1) == 0;
        const int  colE = 16 * ((0)) ; (void)colE;
#pragma unroll
        for (int ntp = 0; ntp < 4; ntp++) {
            const int ntA = 2 * ntp, ntB = ntA + 1;
            const int col = ev ? (16 * ntp + 2 * tig) : (16 * ntp + 8 + 2 * (tig - 1));
#pragma unroll
            for (int hseg = 0; hseg < 2; hseg++) {   // 0: row g (c0,c1), 1: row g+8 (c2,c3)
                float m0 = acc[ntA][2 * hseg], m1 = acc[ntA][2 * hseg + 1];
                float b0 = acc[ntB][2 * hseg], b1 = acc[ntB][2 * hseg + 1];
                float s0 = ev ? b0 : m0;
                float s1 = ev ? b1 : m1;
                float r0 = __shfl_xor_sync(0xFFFFFFFFu, s0, 1);
                float r1 = __shfl_xor_sync(0xFFFFFFFFu, s1, 1);
                float4 v;
                if (ev) v = make_float4(m0, m1, r0, r1);
                else    v = make_float4(r0, r1, b0, b1);
                const int row = hseg ? rowHi : rowLo;
                if (row < npts)
                    *reinterpret_cast<float4*>(out + (size_t)row * COUT_ + col) = v;
            }
        }
        __syncwarp();   // A region consumed; safe to overwrite next iteration
    }
}

extern "C" void kernel_launch(void* const* d_in, const int* in_sizes, int n_in,
                              void* d_out, int out_size)
{
    const float *x = nullptr, *kp = nullptr, *wt = nullptr, *sg = nullptr;
    int x_elems = 0;
    for (int i = 0; i < n_in; i++) {
        int s = in_sizes[i];
        if (s == 1)                    sg = (const float*)d_in[i];
        else if (s == JDIM)            kp = (const float*)d_in[i];
        else if (s == KP_ * 3 * COUT_) wt = (const float*)d_in[i];
        else { x = (const float*)d_in[i]; x_elems = s; }
    }
    const int npts   = x_elems / 3;
    const int groups = (npts + 15) >> 4;
    int grid = 148 * 3;
    int maxg = (groups + 3) / 4;
    if (grid > maxg) grid = maxg;

    kpconv_wmma2_kernel<<<grid, NTHR>>>(x, kp, wt, sg, (float*)d_out, npts);
}

// round 7
// speedup vs baseline: 1.9941x; 1.0556x over previous
#include <cuda_runtime.h>
#include <cuda_bf16.h>
#include <cstdint>

// KPConv as warp-MMA GEMM with warp-pairing + double-buffered A staging:
//   A[p, j] = exp(-0.5*d2(p,k)/sigma^2) * x[p,i]  (j=3k+i, 48 cols = 3 k-tiles)
//   out = A @ W.  fp32 via bf16 split: D = Ah*Wh + Al*Wh + Ah*Wl.
// A pair of warps owns a 32-row group: each warp builds its own 16-row A tile
// (hi/lo bf16, stride 144B), then computes its 32-col n-half of BOTH tiles.
// One named bar.sync(64) per iteration (double buffer makes it sufficient).

#define KP_    16
#define JDIM   48
#define COUT_  64
#define NTHR   128
#define ROWB   144
#define AWARP  (16 * ROWB)   // 2304 B per (warp, half)

__device__ __forceinline__ uint32_t smem_u32(const void* p) {
    uint32_t a;
    asm("{ .reg .u64 t; cvta.to.shared.u64 t, %1; cvt.u32.u64 %0, t; }" : "=r"(a) : "l"(p));
    return a;
}
__device__ __forceinline__ uint32_t pack_bf_rn(float lo, float hi) {
    uint32_t r;
    asm("cvt.rn.bf16x2.f32 %0, %1, %2;" : "=r"(r) : "f"(hi), "f"(lo));
    return r;
}
__device__ __forceinline__ void ldsm_x4(uint32_t* r, uint32_t addr) {
    asm volatile("ldmatrix.sync.aligned.m8n8.x4.shared.b16 {%0,%1,%2,%3}, [%4];"
                 : "=r"(r[0]), "=r"(r[1]), "=r"(r[2]), "=r"(r[3]) : "r"(addr));
}
__device__ __forceinline__ void mma_bf16(float* c, const uint32_t* a, const uint32_t* b) {
    asm volatile(
        "mma.sync.aligned.m16n8k16.row.col.f32.bf16.bf16.f32 "
        "{%0,%1,%2,%3}, {%4,%5,%6,%7}, {%8,%9}, {%0,%1,%2,%3};"
        : "+f"(c[0]), "+f"(c[1]), "+f"(c[2]), "+f"(c[3])
        : "r"(a[0]), "r"(a[1]), "r"(a[2]), "r"(a[3]), "r"(b[0]), "r"(b[1]));
}
__device__ __forceinline__ void bar_pair(int id) {
    asm volatile("bar.sync %0, 64;" :: "r"(id) : "memory");
}

__global__ __launch_bounds__(NTHR, 4)
void kpconv_wmma3_kernel(const float* __restrict__ x,
                         const float* __restrict__ kpts,
                         const float* __restrict__ wts,
                         const float* __restrict__ sigma,
                         float* __restrict__ out,
                         int npts)
{
    // [buf][warp][hi/lo][16 rows x 144B] = 36864 B; W (12288B) staged aliased.
    __shared__ __align__(16) char sA[2][4][2][AWARP];
    __shared__ float sKP[JDIM];

    const int tid  = threadIdx.x;
    const int wid  = tid >> 5;
    const int lane = tid & 31;
    const int gid  = lane >> 2;     // 0..7
    const int tig  = lane & 3;      // 0..3
    const int pr   = wid >> 1;      // pair id 0/1
    const int j    = wid & 1;       // n-half within pair
    const int colbase = 32 * j;

    if (tid < JDIM) sKP[tid] = kpts[tid];

    // ---- one-time: stage W (aliased into sA), build this lane's B frags ----
    float* sWf = reinterpret_cast<float*>(&sA[0][0][0][0]);
    for (int i = tid; i < JDIM * COUT_; i += NTHR) sWf[i] = wts[i];
    __syncthreads();

    uint32_t Bh[4][3][2], Bl[4][3][2];
#pragma unroll
    for (int nt = 0; nt < 4; nt++) {
#pragma unroll
        for (int kt = 0; kt < 3; kt++) {
            int n  = colbase + nt * 8 + gid;
            int j0 = kt * 16 + 2 * tig;
#pragma unroll
            for (int h = 0; h < 2; h++) {
                float w0 = sWf[(j0 + 8 * h    ) * COUT_ + n];
                float w1 = sWf[(j0 + 8 * h + 1) * COUT_ + n];
                float h0 = __bfloat162float(__float2bfloat16_rn(w0));
                float h1 = __bfloat162float(__float2bfloat16_rn(w1));
                Bh[nt][kt][h] = pack_bf_rn(h0, h1);
                Bl[nt][kt][h] = pack_bf_rn(w0 - h0, w1 - h1);
            }
        }
    }

    // ---- hoist my 8 kernel points into registers (loop-invariant) ----
    const int k0 = (lane & 1) * 8;
    float kpx[8], kpy[8], kpz[8];
#pragma unroll
    for (int kk = 0; kk < 8; kk++) {
        kpx[kk] = sKP[3 * (k0 + kk) + 0];
        kpy[kk] = sKP[3 * (k0 + kk) + 1];
        kpz[kk] = sKP[3 * (k0 + kk) + 2];
    }
    __syncthreads();   // W staging dead; sA belongs to pairs now

    const float sg = sigma[0];
    const float cc = -0.5f / (sg * sg);

    // ldmatrix lane offset within a 16-row tile
    const uint32_t lmoff = (uint32_t)(lane & 15) * ROWB + (uint32_t)(lane >> 4) * 16;
    const uint32_t sbase = smem_u32(&sA[0][0][0][0]);

    const int ngroups = (npts + 31) >> 5;                  // 32-row groups
    const int g0      = blockIdx.x * 2 + pr;
    const int gstep   = gridDim.x * 2;
    const int barid   = pr + 1;

    int buf = 0;
    for (int grp = g0; grp < ngroups; grp += gstep, buf ^= 1) {
        const int rowbase = grp << 5;

        // ---- phase 1: build my 16-row tile (rows rowbase + j*16 + r) ----
        {
            const int r = lane >> 1;
            const int p = rowbase + j * 16 + r;
            float x0 = 0.f, x1 = 0.f, x2 = 0.f;
            if (p < npts) { x0 = x[3 * p]; x1 = x[3 * p + 1]; x2 = x[3 * p + 2]; }
            float g[8];
#pragma unroll
            for (int kk = 0; kk < 8; kk++) {
                float dx = x0 - kpx[kk], dy = x1 - kpy[kk], dz = x2 - kpz[kk];
                g[kk] = __expf(cc * (dx * dx + dy * dy + dz * dz));
            }
            float a[24];
#pragma unroll
            for (int kk = 0; kk < 8; kk++) {
                a[3 * kk] = g[kk] * x0; a[3 * kk + 1] = g[kk] * x1; a[3 * kk + 2] = g[kk] * x2;
            }
            uint32_t hv[12], lv[12];
#pragma unroll
            for (int m = 0; m < 12; m++) {
                float ae = a[2 * m], ao = a[2 * m + 1];
                float he = __uint_as_float(__float_as_uint(ae) & 0xFFFF0000u);
                float ho = __uint_as_float(__float_as_uint(ao) & 0xFFFF0000u);
                asm("prmt.b32 %0, %1, %2, 0x7632;"
                    : "=r"(hv[m]) : "r"(__float_as_uint(ae)), "r"(__float_as_uint(ao)));
                lv[m] = pack_bf_rn(ae - he, ao - ho);
            }
            char* rh = &sA[buf][wid][0][0] + r * ROWB + (lane & 1) * 48;
            char* rl = &sA[buf][wid][1][0] + r * ROWB + (lane & 1) * 48;
#pragma unroll
            for (int q = 0; q < 3; q++) {
                *reinterpret_cast<uint4*>(rh + q * 16) =
                    make_uint4(hv[4 * q], hv[4 * q + 1], hv[4 * q + 2], hv[4 * q + 3]);
                *reinterpret_cast<uint4*>(rl + q * 16) =
                    make_uint4(lv[4 * q], lv[4 * q + 1], lv[4 * q + 2], lv[4 * q + 3]);
            }
        }
        bar_pair(barid);   // pair-wide: both tiles of this group are ready

        // ---- phase 2: my 32-col n-half of both 16-row tiles ----
        float acc[2][4][4];
#pragma unroll
        for (int t = 0; t < 2; t++)
#pragma unroll
            for (int nt = 0; nt < 4; nt++)
#pragma unroll
                for (int c = 0; c < 4; c++) acc[t][nt][c] = 0.f;

#pragma unroll
        for (int t = 0; t < 2; t++) {
            const int ownerw = 2 * pr + t;
            const uint32_t aHi = sbase + ((uint32_t)(buf * 8 + ownerw * 2 + 0)) * AWARP + lmoff;
            const uint32_t aLo = sbase + ((uint32_t)(buf * 8 + ownerw * 2 + 1)) * AWARP + lmoff;
#pragma unroll
            for (int kt = 0; kt < 3; kt++) {
                uint32_t ah[4], al[4];
                ldsm_x4(ah, aHi + kt * 32);
                ldsm_x4(al, aLo + kt * 32);
#pragma unroll
                for (int nt = 0; nt < 4; nt++) mma_bf16(acc[t][nt], ah, Bh[nt][kt]);
#pragma unroll
                for (int nt = 0; nt < 4; nt++) mma_bf16(acc[t][nt], al, Bh[nt][kt]);
#pragma unroll
                for (int nt = 0; nt < 4; nt++) mma_bf16(acc[t][nt], ah, Bl[nt][kt]);
            }
        }

        // ---- epilogue: butterfly (xor 1) -> float4 -> STG.128 ----
        const bool ev = (tig & 1) == 0;
#pragma unroll
        for (int t = 0; t < 2; t++) {
            const int rowLo = rowbase + 16 * t + gid;
            const int rowHi = rowLo + 8;
#pragma unroll
            for (int ntp = 0; ntp < 2; ntp++) {
                const int ntA = 2 * ntp, ntB = ntA + 1;
                const int col = colbase +
                    (ev ? (16 * ntp + 2 * tig) : (16 * ntp + 8 + 2 * (tig - 1)));
#pragma unroll
                for (int hseg = 0; hseg < 2; hseg++) {
                    float m0 = acc[t][ntA][2 * hseg], m1 = acc[t][ntA][2 * hseg + 1];
                    float b0 = acc[t][ntB][2 * hseg], b1 = acc[t][ntB][2 * hseg + 1];
                    float s0 = ev ? b0 : m0;
                    float s1 = ev ? b1 : m1;
                    float r0 = __shfl_xor_sync(0xFFFFFFFFu, s0, 1);
                    float r1 = __shfl_xor_sync(0xFFFFFFFFu, s1, 1);
                    float4 v;
                    if (ev) v = make_float4(m0, m1, r0, r1);
                    else    v = make_float4(r0, r1, b0, b1);
                    const int row = hseg ? rowHi : rowLo;
                    if (row < npts)
                        *reinterpret_cast<float4*>(out + (size_t)row * COUT_ + col) = v;
                }
            }
        }
        // no second barrier: double buffering + next iteration's bar orders reuse
    }
}

extern "C" void kernel_launch(void* const* d_in, const int* in_sizes, int n_in,
                              void* d_out, int out_size)
{
    const float *x = nullptr, *kp = nullptr, *wt = nullptr, *sg = nullptr;
    int x_elems = 0;
    for (int i = 0; i < n_in; i++) {
        int s = in_sizes[i];
        if (s == 1)                    sg = (const float*)d_in[i];
        else if (s == JDIM)            kp = (const float*)d_in[i];
        else if (s == KP_ * 3 * COUT_) wt = (const float*)d_in[i];
        else { x = (const float*)d_in[i]; x_elems = s; }
    }
    const int npts    = x_elems / 3;
    const int ngroups = (npts + 31) >> 5;
    int grid = 148 * 4;
    int maxg = (ngroups + 1) / 2;
    if (grid > maxg) grid = maxg;

    kpconv_wmma3_kernel<<<grid, NTHR>>>(x, kp, wt, sg, (float*)d_out, npts);
}